// round 3
// baseline (speedup 1.0000x reference)
#include <cuda_runtime.h>

constexpr int NMAX  = 100000;
constexpr int EMAX  = 1600000;
constexpr int D_IN  = 16;
constexpr int D_HID = 32;
constexpr int D_OUT = 16;

// Scratch (__device__ globals; allocation-free rule). Zero-initialized at load.
__device__ alignas(16) float g_pre[NMAX * D_IN];    // emb[x[v]] * dinv[v]
__device__ alignas(16) float g_hs2[NMAX * D_OUT];   // (relu(conv1)@W2) * dinv
__device__ float g_dinv[NMAX];
__device__ int   g_deg [NMAX];      // must be 0 at entry; re-zeroed by scan_c
__device__ int   g_row [NMAX];      // CSR row start (bucketed by dst)
__device__ int   g_cur [NMAX];      // fill cursor; after fill == row end
__device__ int   g_csr [EMAX];      // src per CSR slot
__device__ int   g_csum[256];
__device__ int   g_coff[256];

// ---------------------------------------------------------------------------
// K1: degree histogram over real edges (deg starts at 0).
__global__ void k_deg(const int* __restrict__ dst, int E) {
    int i = blockIdx.x * blockDim.x + threadIdx.x;
    int e4 = i * 4;
    if (e4 + 3 < E) {
        int4 d = *reinterpret_cast<const int4*>(dst + e4);
        atomicAdd(&g_deg[d.x], 1); atomicAdd(&g_deg[d.y], 1);
        atomicAdd(&g_deg[d.z], 1); atomicAdd(&g_deg[d.w], 1);
    } else {
        for (int e = e4; e < E && e >= 0; e++) atomicAdd(&g_deg[dst[e]], 1);
    }
}

// ---- exclusive scan of g_deg -> g_row (chunk = 512 elems) ------------------
__global__ void k_scan_a(int n) {
    int t = threadIdx.x;
    int i0 = blockIdx.x * 512 + 2 * t;
    int p = ((i0 < n) ? g_deg[i0] : 0) + ((i0 + 1 < n) ? g_deg[i0 + 1] : 0);
#pragma unroll
    for (int o = 16; o > 0; o >>= 1) p += __shfl_down_sync(~0u, p, o);
    __shared__ int ws[8];
    if ((t & 31) == 0) ws[t >> 5] = p;
    __syncthreads();
    if (t == 0) {
        int s = 0;
#pragma unroll
        for (int w = 0; w < 8; w++) s += ws[w];
        g_csum[blockIdx.x] = s;
    }
}

__global__ void k_scan_b(int nchunks) {
    __shared__ int sm[256];
    int t = threadIdx.x;
    int v = (t < nchunks) ? g_csum[t] : 0;
    sm[t] = v;
    __syncthreads();
#pragma unroll
    for (int o = 1; o < 256; o <<= 1) {
        int x = (t >= o) ? sm[t - o] : 0;
        __syncthreads();
        sm[t] += x;
        __syncthreads();
    }
    g_coff[t] = sm[t] - v;   // exclusive
}

// K4: finish scan; also compute dinv, pre = emb[x[v]]*dinv, and re-zero deg.
__global__ void k_scan_c(const int* __restrict__ x, const float* __restrict__ emb,
                         int n) {
    int t = threadIdx.x, lane = t & 31, w = t >> 5;
    int i0 = blockIdx.x * 512 + 2 * t;
    int d0 = (i0 < n) ? g_deg[i0] : 0;
    int d1 = (i0 + 1 < n) ? g_deg[i0 + 1] : 0;
    int p = d0 + d1, incl = p;
#pragma unroll
    for (int o = 1; o < 32; o <<= 1) {
        int xx = __shfl_up_sync(~0u, incl, o);
        if (lane >= o) incl += xx;
    }
    __shared__ int ws[8];
    if (lane == 31) ws[w] = incl;
    __syncthreads();
    if (t == 0) {
        int run = 0;
#pragma unroll
        for (int i = 0; i < 8; i++) { int tmp = ws[i]; ws[i] = run; run += tmp; }
    }
    __syncthreads();
    int excl = incl - p + ws[w] + g_coff[blockIdx.x];

#pragma unroll
    for (int u = 0; u < 2; u++) {
        int v = i0 + u;
        if (v >= n) break;
        int d = (u == 0) ? d0 : d1;
        int st = (u == 0) ? excl : excl + d0;
        g_row[v] = st;
        g_cur[v] = st;
        g_deg[v] = 0;                              // reset for next replay
        float dinv = rsqrtf((float)(d + 1));       // +1 self-loop
        g_dinv[v] = dinv;
        int xr = x[v];
        const float4* er = reinterpret_cast<const float4*>(emb + (size_t)xr * D_IN);
        float4* pr = reinterpret_cast<float4*>(g_pre + (size_t)v * D_IN);
#pragma unroll
        for (int q = 0; q < D_IN / 4; q++) {
            float4 e = er[q];
            pr[q] = make_float4(e.x * dinv, e.y * dinv, e.z * dinv, e.w * dinv);
        }
    }
}

// K5: bucket fill: csr[pos] = src for each edge, bucketed by dst.
__global__ void k_fill(const int* __restrict__ src, const int* __restrict__ dst,
                       int E) {
    int e = blockIdx.x * blockDim.x + threadIdx.x;
    if (e >= E) return;
    int d = dst[e];
    int pos = atomicAdd(&g_cur[d], 1);
    g_csr[pos] = src[e];
}

// K6: layer-1 aggregation (16-dim) + fused W1/relu GEMM + fused W2*dinv GEMM.
// One warp per node. Row = 16 floats = 4 float4; chunk = lane&3, sub = lane>>2.
__global__ void k_agg1(const float* __restrict__ W1, const float* __restrict__ b1,
                       const float* __restrict__ W2, int n) {
    __shared__ float W1s[D_IN * D_HID];
    __shared__ float W2s[D_HID * D_OUT];
    __shared__ float b1s[D_HID];
    for (int t = threadIdx.x; t < D_IN * D_HID; t += blockDim.x) W1s[t] = W1[t];
    for (int t = threadIdx.x; t < D_HID * D_OUT; t += blockDim.x) W2s[t] = W2[t];
    if (threadIdx.x < D_HID) b1s[threadIdx.x] = b1[threadIdx.x];
    __syncthreads();

    int gw = (blockIdx.x * blockDim.x + threadIdx.x) >> 5;
    if (gw >= n) return;
    int v = gw;
    int lane = threadIdx.x & 31;
    int chunk = lane & 3;
    int sub   = lane >> 2;

    int start = g_row[v], end = g_cur[v];
    float4 acc = make_float4(0.f, 0.f, 0.f, 0.f);
    for (int j = start + sub; j < end; j += 8) {
        int s = __ldg(&g_csr[j]);
        float4 t = *reinterpret_cast<const float4*>(g_pre + ((size_t)s * D_IN) + chunk * 4);
        acc.x += t.x; acc.y += t.y; acc.z += t.z; acc.w += t.w;
    }
#pragma unroll
    for (int o = 4; o <= 16; o <<= 1) {
        acc.x += __shfl_xor_sync(~0u, acc.x, o);
        acc.y += __shfl_xor_sync(~0u, acc.y, o);
        acc.z += __shfl_xor_sync(~0u, acc.z, o);
        acc.w += __shfl_xor_sync(~0u, acc.w, o);
    }
    float dinv = g_dinv[v];
    float4 self = *reinterpret_cast<const float4*>(g_pre + (size_t)v * D_IN + chunk * 4);
    acc.x = (acc.x + self.x) * dinv;
    acc.y = (acc.y + self.y) * dinv;
    acc.z = (acc.z + self.z) * dinv;
    acc.w = (acc.w + self.w) * dinv;

    // Broadcast aggregated 16-vector to all lanes (lane c holds chunk c).
    float a[D_IN];
#pragma unroll
    for (int c = 0; c < 4; c++) {
        a[4 * c + 0] = __shfl_sync(~0u, acc.x, c);
        a[4 * c + 1] = __shfl_sync(~0u, acc.y, c);
        a[4 * c + 2] = __shfl_sync(~0u, acc.z, c);
        a[4 * c + 3] = __shfl_sync(~0u, acc.w, c);
    }
    // r_j = relu(a @ W1 + b1), lane j = column j of W1 (j = 0..31).
    float r = b1s[lane];
#pragma unroll
    for (int k = 0; k < D_IN; k++) r = fmaf(a[k], W1s[k * D_HID + lane], r);
    r = fmaxf(r, 0.f);

    // hs2_j' = dinv * (r @ W2), j' = lane & 15 (lanes 16-31 redundant).
    float h = 0.f;
#pragma unroll
    for (int k = 0; k < D_HID; k++)
        h = fmaf(__shfl_sync(~0u, r, k), W2s[k * D_OUT + (lane & 15)], h);
    h *= dinv;
    if (lane < D_OUT) g_hs2[(size_t)v * D_OUT + lane] = h;
}

// K7: layer-2 aggregation (16-dim) + bias -> out.
__global__ void k_agg2(const float* __restrict__ b2, float* __restrict__ out, int n) {
    int gw = (blockIdx.x * blockDim.x + threadIdx.x) >> 5;
    if (gw >= n) return;
    int v = gw;
    int lane = threadIdx.x & 31;
    int chunk = lane & 3;
    int sub   = lane >> 2;

    int start = g_row[v], end = g_cur[v];
    float4 acc = make_float4(0.f, 0.f, 0.f, 0.f);
    for (int j = start + sub; j < end; j += 8) {
        int s = __ldg(&g_csr[j]);
        float4 t = *reinterpret_cast<const float4*>(g_hs2 + ((size_t)s * D_OUT) + chunk * 4);
        acc.x += t.x; acc.y += t.y; acc.z += t.z; acc.w += t.w;
    }
#pragma unroll
    for (int o = 4; o <= 16; o <<= 1) {
        acc.x += __shfl_xor_sync(~0u, acc.x, o);
        acc.y += __shfl_xor_sync(~0u, acc.y, o);
        acc.z += __shfl_xor_sync(~0u, acc.z, o);
        acc.w += __shfl_xor_sync(~0u, acc.w, o);
    }
    if (sub == 0) {
        float dinv = g_dinv[v];
        float4 self = *reinterpret_cast<const float4*>(g_hs2 + (size_t)v * D_OUT + chunk * 4);
        float4 bb = *reinterpret_cast<const float4*>(b2 + chunk * 4);
        float4 r;
        r.x = dinv * (acc.x + self.x) + bb.x;
        r.y = dinv * (acc.y + self.y) + bb.y;
        r.z = dinv * (acc.z + self.z) + bb.z;
        r.w = dinv * (acc.w + self.w) + bb.w;
        *reinterpret_cast<float4*>(out + (size_t)v * D_OUT + chunk * 4) = r;
    }
}

extern "C" void kernel_launch(void* const* d_in, const int* in_sizes, int n_in,
                              void* d_out, int out_size) {
    const int*   x   = (const int*)  d_in[0];
    const int*   ei  = (const int*)  d_in[1];   // [2, E]: src then dst
    const float* emb = (const float*)d_in[2];
    const float* W1  = (const float*)d_in[3];
    const float* b1  = (const float*)d_in[4];
    const float* W2  = (const float*)d_in[5];
    const float* b2  = (const float*)d_in[6];
    float* out = (float*)d_out;

    int n = in_sizes[0];
    int E = in_sizes[1] / 2;
    const int* src = ei;
    const int* dst = ei + E;

    const int B = 256;
    int nchunks = (n + 511) / 512;

    k_deg   <<<(E / 4 + B - 1) / B + 1, B>>>(dst, E);
    k_scan_a<<<nchunks, 256>>>(n);
    k_scan_b<<<1, 256>>>(nchunks);
    k_scan_c<<<nchunks, 256>>>(x, emb, n);
    k_fill  <<<(E + B - 1) / B, B>>>(src, dst, E);

    int warp_threads = n * 32;
    k_agg1  <<<(warp_threads + B - 1) / B, B>>>(W1, b1, W2, n);
    k_agg2  <<<(warp_threads + B - 1) / B, B>>>(b2, out, n);
}

// round 4
// speedup vs baseline: 1.4164x; 1.4164x over previous
#include <cuda_runtime.h>

constexpr int NMAX  = 100000;
constexpr int D_IN  = 16;
constexpr int D_HID = 32;
constexpr int D_OUT = 16;

// Scratch (__device__ globals; allocation-free rule). Zero-initialized at load.
__device__ alignas(16) float g_pre [NMAX * D_IN];   // emb[x[v]] * dinv[v]
__device__ alignas(16) float g_agg1[NMAX * D_IN];   // self + Sum over in-edges
__device__ alignas(16) float g_hs2 [NMAX * D_OUT];  // (relu(conv1)@W2) * dinv
__device__ alignas(16) float g_agg2[NMAX * D_OUT];  // self + Sum over in-edges
__device__ float g_dinv[NMAX];
__device__ int   g_deg [NMAX];   // 0 at entry (static init / reset by k_pre)

// ---------------------------------------------------------------------------
// K1: degree histogram over real edges (self-loop folded as +1 in k_pre).
__global__ void k_deg(const int* __restrict__ dst, int E) {
    int i = blockIdx.x * blockDim.x + threadIdx.x;
    int e4 = i * 4;
    if (e4 + 3 < E) {
        int4 d = *reinterpret_cast<const int4*>(dst + e4);
        atomicAdd(&g_deg[d.x], 1); atomicAdd(&g_deg[d.y], 1);
        atomicAdd(&g_deg[d.z], 1); atomicAdd(&g_deg[d.w], 1);
    } else {
        for (int e = e4; e < E && e >= 0; e++) atomicAdd(&g_deg[dst[e]], 1);
    }
}

// K2: per node: dinv; pre = emb[x[v]]*dinv; agg1 = pre (self-loop seed);
//     reset deg for next graph replay.
__global__ void k_pre(const int* __restrict__ x, const float* __restrict__ emb,
                      int n) {
    int v = blockIdx.x * blockDim.x + threadIdx.x;
    if (v >= n) return;
    int d = g_deg[v];
    g_deg[v] = 0;
    float dinv = rsqrtf((float)(d + 1));
    g_dinv[v] = dinv;
    int xr = x[v];
    const float4* er = reinterpret_cast<const float4*>(emb + (size_t)xr * D_IN);
    float4* pr = reinterpret_cast<float4*>(g_pre  + (size_t)v * D_IN);
    float4* ar = reinterpret_cast<float4*>(g_agg1 + (size_t)v * D_IN);
#pragma unroll
    for (int q = 0; q < D_IN / 4; q++) {
        float4 e = er[q];
        float4 p = make_float4(e.x * dinv, e.y * dinv, e.z * dinv, e.w * dinv);
        pr[q] = p;
        ar[q] = p;
    }
}

// K3/K5: edge scatter in 16-dim space: 4 threads per edge, red.v4 per thread.
// IN/OUT selected by template to keep device-symbol addressing in device code.
template <int LAYER>
__global__ void k_scatter(const int* __restrict__ src, const int* __restrict__ dst,
                          int E) {
    const float* in  = (LAYER == 1) ? g_pre  : g_hs2;
    float*       out = (LAYER == 1) ? g_agg1 : g_agg2;

    long long t = (long long)blockIdx.x * blockDim.x + threadIdx.x;
    int e = (int)(t >> 2);
    if (e >= E) return;
    int c = (int)t & 3;

    int s = __ldg(&src[e]);
    int d = __ldg(&dst[e]);

    float4 v = *reinterpret_cast<const float4*>(in + ((size_t)s << 4) + c * 4);
    float* p = out + ((size_t)d << 4) + c * 4;
    asm volatile("red.global.add.v4.f32 [%0], {%1,%2,%3,%4};"
                 :: "l"(p), "f"(v.x), "f"(v.y), "f"(v.z), "f"(v.w) : "memory");
}

// K4: per node: a = agg1*dinv; r = relu(a@W1 + b1); hs2 = (r@W2)*dinv;
//     agg2 = hs2 (self-loop seed).
__global__ void k_mid(const float* __restrict__ W1, const float* __restrict__ b1,
                      const float* __restrict__ W2, int n) {
    __shared__ float W1s[D_IN * D_HID];
    __shared__ float W2s[D_HID * D_OUT];
    __shared__ float b1s[D_HID];
    for (int t = threadIdx.x; t < D_IN * D_HID; t += blockDim.x) W1s[t] = W1[t];
    for (int t = threadIdx.x; t < D_HID * D_OUT; t += blockDim.x) W2s[t] = W2[t];
    if (threadIdx.x < D_HID) b1s[threadIdx.x] = b1[threadIdx.x];
    __syncthreads();

    int v = blockIdx.x * blockDim.x + threadIdx.x;
    if (v >= n) return;

    float dinv = g_dinv[v];
    float a[D_IN];
    const float4* ar = reinterpret_cast<const float4*>(g_agg1 + (size_t)v * D_IN);
#pragma unroll
    for (int q = 0; q < D_IN / 4; q++) {
        float4 t = ar[q];
        a[q*4+0] = t.x * dinv; a[q*4+1] = t.y * dinv;
        a[q*4+2] = t.z * dinv; a[q*4+3] = t.w * dinv;
    }

    float r[D_HID];
#pragma unroll
    for (int j = 0; j < D_HID; j++) r[j] = b1s[j];
#pragma unroll
    for (int k = 0; k < D_IN; k++) {
        float av = a[k];
#pragma unroll
        for (int j = 0; j < D_HID; j++) r[j] = fmaf(av, W1s[k * D_HID + j], r[j]);
    }
#pragma unroll
    for (int j = 0; j < D_HID; j++) r[j] = fmaxf(r[j], 0.f);

    float h[D_OUT];
#pragma unroll
    for (int j = 0; j < D_OUT; j++) h[j] = 0.f;
#pragma unroll
    for (int k = 0; k < D_HID; k++) {
        float rv = r[k];
#pragma unroll
        for (int j = 0; j < D_OUT; j++) h[j] = fmaf(rv, W2s[k * D_OUT + j], h[j]);
    }

    float4* hr = reinterpret_cast<float4*>(g_hs2  + (size_t)v * D_OUT);
    float4* gr = reinterpret_cast<float4*>(g_agg2 + (size_t)v * D_OUT);
#pragma unroll
    for (int q = 0; q < D_OUT / 4; q++) {
        float4 t = make_float4(h[q*4+0]*dinv, h[q*4+1]*dinv,
                               h[q*4+2]*dinv, h[q*4+3]*dinv);
        hr[q] = t;
        gr[q] = t;
    }
}

// K6: per node: out = agg2*dinv + b2.
__global__ void k_post(const float* __restrict__ b2, float* __restrict__ out, int n) {
    int v = blockIdx.x * blockDim.x + threadIdx.x;
    if (v >= n) return;
    float dinv = g_dinv[v];
    const float4* ar = reinterpret_cast<const float4*>(g_agg2 + (size_t)v * D_OUT);
    float4* o = reinterpret_cast<float4*>(out + (size_t)v * D_OUT);
#pragma unroll
    for (int q = 0; q < D_OUT / 4; q++) {
        float4 a = ar[q];
        float bx = __ldg(&b2[q*4+0]), by = __ldg(&b2[q*4+1]);
        float bz = __ldg(&b2[q*4+2]), bw = __ldg(&b2[q*4+3]);
        o[q] = make_float4(dinv * a.x + bx, dinv * a.y + by,
                           dinv * a.z + bz, dinv * a.w + bw);
    }
}

extern "C" void kernel_launch(void* const* d_in, const int* in_sizes, int n_in,
                              void* d_out, int out_size) {
    const int*   x   = (const int*)  d_in[0];
    const int*   ei  = (const int*)  d_in[1];   // [2, E]: src then dst
    const float* emb = (const float*)d_in[2];
    const float* W1  = (const float*)d_in[3];
    const float* b1  = (const float*)d_in[4];
    const float* W2  = (const float*)d_in[5];
    const float* b2  = (const float*)d_in[6];
    float* out = (float*)d_out;

    int n = in_sizes[0];
    int E = in_sizes[1] / 2;
    const int* src = ei;
    const int* dst = ei + E;

    const int B = 256;
    int nb_node = (n + B - 1) / B;
    long long et = (long long)E * 4;
    int nb_edge = (int)((et + B - 1) / B);

    k_deg       <<<(E / 4 + B - 1) / B + 1, B>>>(dst, E);
    k_pre       <<<nb_node, B>>>(x, emb, n);
    k_scatter<1><<<nb_edge, B>>>(src, dst, E);
    k_mid       <<<nb_node, B>>>(W1, b1, W2, n);
    k_scatter<2><<<nb_edge, B>>>(src, dst, E);
    k_post      <<<nb_node, B>>>(b2, out, n);
}